// round 4
// baseline (speedup 1.0000x reference)
#include <cuda_runtime.h>
#include <cuda_bf16.h>
#include <cstdint>

// Problem constants (fixed by the reference).
#define NH      128          // feature dim H
#define N_MAX   100000
#define E_MAX   400000
#define KP1     6            // K+1 coefficients per group
#define RMS_EPS 1.1920929e-07f

// -------- static device scratch (allocation-free rule) --------
__device__ int   g_deg [N_MAX];
__device__ int   g_off [N_MAX];
__device__ int   g_fill[N_MAX];
__device__ int   g_col [E_MAX];
__device__ float g_wgt [E_MAX];
__device__ float g_Ta[(size_t)N_MAX * NH];
__device__ float g_Tb[(size_t)N_MAX * NH];
__device__ int   g_part[256];

// -------------------- CSR build --------------------
__global__ void k_zero_deg(int n) {
    int i = blockIdx.x * blockDim.x + threadIdx.x;
    if (i < n) g_deg[i] = 0;
}

// edge_index is int32 (JAX x64 disabled): src = ei[e], dst = ei[E + e]
__global__ void k_hist(const int* __restrict__ ei, int E, int n) {
    for (int e = blockIdx.x * blockDim.x + threadIdx.x; e < E;
         e += gridDim.x * blockDim.x) {
        int d = ei[E + e];
        if (d >= 0 && d < n) atomicAdd(&g_deg[d], 1);
    }
}

// Block-local exclusive scan of degrees (1024 elems/block).
__global__ void k_scan1(int n) {
    __shared__ int s[1024];
    int tid = threadIdx.x;
    int i = blockIdx.x * 1024 + tid;
    int v = (i < n) ? g_deg[i] : 0;
    s[tid] = v;
    __syncthreads();
    for (int off = 1; off < 1024; off <<= 1) {
        int t = (tid >= off) ? s[tid - off] : 0;
        __syncthreads();
        s[tid] += t;
        __syncthreads();
    }
    if (i < n) g_off[i] = s[tid] - v;               // exclusive
    if (tid == 1023) g_part[blockIdx.x] = s[1023];  // block total
}

// Exclusive scan of the (<=256) block partials, single block.
__global__ void k_scan2(int nb) {
    __shared__ int s[256];
    int tid = threadIdx.x;
    int v = (tid < nb) ? g_part[tid] : 0;
    s[tid] = v;
    __syncthreads();
    for (int off = 1; off < 256; off <<= 1) {
        int t = (tid >= off) ? s[tid - off] : 0;
        __syncthreads();
        s[tid] += t;
        __syncthreads();
    }
    if (tid < nb) g_part[tid] = s[tid] - v;         // exclusive
}

__global__ void k_scan3(int n) {
    int i = blockIdx.x * blockDim.x + threadIdx.x;
    if (i < n) {
        int o = g_off[i] + g_part[i >> 10];
        g_off[i]  = o;
        g_fill[i] = o;
    }
}

__global__ void k_scatter(const int* __restrict__ ei,
                          const float* __restrict__ ew, int E, int n) {
    for (int e = blockIdx.x * blockDim.x + threadIdx.x; e < E;
         e += gridDim.x * blockDim.x) {
        int d = ei[E + e];
        int s = ei[e];
        if (d >= 0 && d < n && s >= 0 && s < n) {
            int pos = atomicAdd(&g_fill[d], 1);
            g_col[pos] = s;
            g_wgt[pos] = ew[e];
        }
    }
}

// -------------------- propagate + combine --------------------
// One warp per node; lane l owns features [4l, 4l+4). Group g = lane>>3.

__device__ __forceinline__ float4 gather_row(const float4* __restrict__ S,
                                             int node, int lane) {
    int start = g_off[node];
    int dn    = g_deg[node];
    float4 acc = make_float4(0.f, 0.f, 0.f, 0.f);
    for (int j = 0; j < dn; j++) {
        int   c = g_col[start + j];
        float w = g_wgt[start + j];
        float4 v = S[(size_t)c * 32 + lane];
        acc.x += w * v.x; acc.y += w * v.y; acc.z += w * v.z; acc.w += w * v.w;
    }
    return acc;
}

// T1 = prop(x); Ta = T1; out = c0*x + c1*T1
__global__ void k_prop_first(const float4* __restrict__ x,
                             const float* __restrict__ cheb,
                             float4* __restrict__ out, int n) {
    int w = (blockIdx.x * blockDim.x + threadIdx.x) >> 5;
    if (w >= n) return;
    int lane = threadIdx.x & 31;
    float4 acc = gather_row(x, w, lane);
    size_t idx = (size_t)w * 32 + lane;
    ((float4*)g_Ta)[idx] = acc;
    int g = lane >> 3;
    float c0 = cheb[g * KP1 + 0];
    float c1 = cheb[g * KP1 + 1];
    float4 xv = x[idx];
    float4 r;
    r.x = c0 * xv.x + c1 * acc.x;
    r.y = c0 * xv.y + c1 * acc.y;
    r.z = c0 * xv.z + c1 * acc.z;
    r.w = c0 * xv.w + c1 * acc.w;
    out[idx] = r;
}

// T_k = 2*prop(Tsrc) - Tp2; Tdst = T_k; out += c_k * T_k
__global__ void k_prop_step(const float4* __restrict__ Tsrc,
                            const float4* __restrict__ Tp2,
                            float4* __restrict__ Tdst,
                            const float* __restrict__ cheb, int k,
                            float4* __restrict__ out, int n) {
    int w = (blockIdx.x * blockDim.x + threadIdx.x) >> 5;
    if (w >= n) return;
    int lane = threadIdx.x & 31;
    float4 acc = gather_row(Tsrc, w, lane);
    size_t idx = (size_t)w * 32 + lane;
    float4 p = Tp2[idx];
    float4 t;
    t.x = 2.f * acc.x - p.x;
    t.y = 2.f * acc.y - p.y;
    t.z = 2.f * acc.z - p.z;
    t.w = 2.f * acc.w - p.w;
    Tdst[idx] = t;
    float ck = cheb[(lane >> 3) * KP1 + k];
    float4 r = out[idx];
    r.x += ck * t.x; r.y += ck * t.y; r.z += ck * t.z; r.w += ck * t.w;
    out[idx] = r;
}

// Final step (k=5) fused with scale/bias + RMSNorm + SiLU. No Tdst store.
__global__ void k_prop_final(const float4* __restrict__ Tsrc,
                             const float4* __restrict__ Tp2,
                             const float* __restrict__ cheb,
                             const float* __restrict__ gscale,
                             const float* __restrict__ gbias,
                             const float4* __restrict__ rmsw,
                             float4* __restrict__ out, int n) {
    int w = (blockIdx.x * blockDim.x + threadIdx.x) >> 5;
    if (w >= n) return;
    int lane = threadIdx.x & 31;
    float4 acc = gather_row(Tsrc, w, lane);
    size_t idx = (size_t)w * 32 + lane;
    float4 p = Tp2[idx];
    float4 t;
    t.x = 2.f * acc.x - p.x;
    t.y = 2.f * acc.y - p.y;
    t.z = 2.f * acc.z - p.z;
    t.w = 2.f * acc.w - p.w;
    int g = lane >> 3;
    float c5 = cheb[g * KP1 + 5];
    float sc = gscale[g];
    float bi = gbias[g];
    float4 r = out[idx];
    r.x = (r.x + c5 * t.x) * sc + bi;
    r.y = (r.y + c5 * t.y) * sc + bi;
    r.z = (r.z + c5 * t.z) * sc + bi;
    r.w = (r.w + c5 * t.w) * sc + bi;
    // RMS over the full 128-wide row (whole row lives in this warp)
    float ss = r.x * r.x + r.y * r.y + r.z * r.z + r.w * r.w;
    #pragma unroll
    for (int o = 16; o > 0; o >>= 1)
        ss += __shfl_xor_sync(0xFFFFFFFFu, ss, o);
    float rms = rsqrtf(ss * (1.0f / NH) + RMS_EPS);
    float4 wv = rmsw[lane];
    float4 o4;
    float y;
    y = r.x * rms * wv.x; o4.x = y / (1.f + __expf(-y));
    y = r.y * rms * wv.y; o4.y = y / (1.f + __expf(-y));
    y = r.z * rms * wv.z; o4.z = y / (1.f + __expf(-y));
    y = r.w * rms * wv.w; o4.w = y / (1.f + __expf(-y));
    out[idx] = o4;
}

// -------------------- launch --------------------
extern "C" void kernel_launch(void* const* d_in, const int* in_sizes, int n_in,
                              void* d_out, int out_size) {
    const float* x    = (const float*)d_in[0];
    const float* ew   = (const float*)d_in[1];
    const float* cheb = (const float*)d_in[2];
    const float* gsc  = (const float*)d_in[3];
    const float* gbi  = (const float*)d_in[4];
    const float* rmsw = (const float*)d_in[5];
    const int*   ei   = (const int*)d_in[6];   // int32! (JAX x64 disabled)

    const int N = in_sizes[0] / NH;
    const int E = in_sizes[1];

    const float4* x4   = (const float4*)x;
    float4*       out4 = (float4*)d_out;
    float4*       Ta   = nullptr;
    float4*       Tb   = nullptr;
    cudaGetSymbolAddress((void**)&Ta, g_Ta);
    cudaGetSymbolAddress((void**)&Tb, g_Tb);

    // ---- CSR build ----
    k_zero_deg<<<(N + 255) / 256, 256>>>(N);
    k_hist<<<512, 256>>>(ei, E, N);
    int nb = (N + 1023) / 1024;
    k_scan1<<<nb, 1024>>>(N);
    k_scan2<<<1, 256>>>(nb);
    k_scan3<<<(N + 255) / 256, 256>>>(N);
    k_scatter<<<512, 256>>>(ei, ew, E, N);

    // ---- 5 fused propagate/combine passes ----
    const int TPB  = 256;                 // 8 warps = 8 nodes per block
    const int grid = (N + 7) / 8;

    k_prop_first<<<grid, TPB>>>(x4, cheb, out4, N);                 // T1 -> Ta
    k_prop_step <<<grid, TPB>>>(Ta, x4, Tb, cheb, 2, out4, N);      // T2 -> Tb
    k_prop_step <<<grid, TPB>>>(Tb, Ta, Ta, cheb, 3, out4, N);      // T3 -> Ta
    k_prop_step <<<grid, TPB>>>(Ta, Tb, Tb, cheb, 4, out4, N);      // T4 -> Tb
    k_prop_final<<<grid, TPB>>>(Tb, Ta, cheb, gsc, gbi,
                                (const float4*)rmsw, out4, N);      // T5 + epilogue
}